// round 12
// baseline (speedup 1.0000x reference)
#include <cuda_runtime.h>
#include <cuda_bf16.h>
#include <cstdint>

// Problem shapes (fixed by the dataset)
#define S_LEN 2048
#define BATCH 16
#define DDIM  2048

// Quarter pipeline over the o-dimension (== stage2's reduction d-dimension).
#define NQ    4
#define QD    512                  // o rows per quarter
#define PCH   8                    // o-chunks per quarter
#define OCH   64                   // rows per chunk
#define PKS   64                   // k-splits per chunk
#define KCH   32                   // d per producer tile
#define WPAD  33                   // sW bank = (row + d) % 32 -> conflict-free
#define SPAD  20                   // sS row stride (80B, 16B-aligned LDS.128)

#define NPROD 512                  // producer blocks (bids 0..511)
#define NCONS 2048                 // consumer blocks
#define NB    (NPROD + NCONS)

// Scratch (device globals: allocation-free, all sync state self-resetting).
__device__ float g_part[NQ][PCH][PKS][OCH][BATCH];  // 8 MB
__device__ float g_altered[BATCH * DDIM];           // [b][o], 128 KB
__device__ int   g_cnt[NQ][PCH];
__device__ int   g_qdone[NQ];
__device__ int   g_s2cnt;

__device__ __forceinline__ void ffma2(uint64_t& d, uint64_t a, uint64_t b) {
    asm("fma.rn.f32x2 %0, %1, %2, %0;" : "+l"(d) : "l"(a), "l"(b));
}

__global__ void __launch_bounds__(128)
attender_fused(const float* __restrict__ state,
               const float* __restrict__ W,
               const float* __restrict__ bias,
               const float* __restrict__ enc,
               float* __restrict__ out)
{
    __shared__ union {
        struct { float sW[OCH][WPAD]; float sS[KCH][SPAD]; } p;  // 11.1 KB
        float alt[QD];                                            // 2 KB
    } sm;
    __shared__ int s_tk;

    const int t   = threadIdx.x;
    const int bid = blockIdx.x;

    if (bid < NPROD) {
        // ================= Producer: quarters in sequence =================
        const int ch = bid >> 6;            // o-chunk within each quarter
        const int ks = bid & 63;            // k-split
        const int d0 = ks * KCH;
        const int row = t & 63;             // local o row
        const int bh  = t >> 6;             // batch half (0: b0-7, 1: b8-15)

        // Stage state slice (quarter-independent): sS[d][b], coalesced f4.
        {
            const int b  = t >> 3;
            const int c4 = t & 7;
            const float4 v = *(const float4*)(state + b * DDIM + d0 + c4 * 4);
            sm.p.sS[c4 * 4 + 0][b] = v.x;
            sm.p.sS[c4 * 4 + 1][b] = v.y;
            sm.p.sS[c4 * 4 + 2][b] = v.z;
            sm.p.sS[c4 * 4 + 3][b] = v.w;
        }

        for (int q = 0; q < NQ; ++q) {
            const int obase = q * QD + ch * OCH;

            __syncthreads();   // protect sW reuse (and sS visibility at q=0)
            // Stage W tile 64 rows x 32 d: 512 f4, 4/thread, coalesced
            // (8 lanes/row, nL=4); STS banks (r + 4c4 + k) % 32 conflict-free.
#pragma unroll
            for (int j = 0; j < 4; ++j) {
                const int g  = j * 128 + t;
                const int r  = g >> 3;
                const int c4 = g & 7;
                const float4 v = *(const float4*)(W + (long)(obase + r) * DDIM
                                                  + d0 + c4 * 4);
                sm.p.sW[r][c4 * 4 + 0] = v.x;
                sm.p.sW[r][c4 * 4 + 1] = v.y;
                sm.p.sW[r][c4 * 4 + 2] = v.z;
                sm.p.sW[r][c4 * 4 + 3] = v.w;
            }
            __syncthreads();

            uint64_t acc[4];                // 8 batch accs as packed f32x2
#pragma unroll
            for (int i = 0; i < 4; ++i) acc[i] = 0ull;

#pragma unroll 8
            for (int d = 0; d < KCH; ++d) {
                const float w = sm.p.sW[row][d];       // bank (row+d)%32
                uint64_t wp;
                asm("mov.b64 %0, {%1, %1};" : "=l"(wp) : "r"(__float_as_uint(w)));
                const ulonglong2 q0 = *(const ulonglong2*)&sm.p.sS[d][bh * 8];
                const ulonglong2 q1 = *(const ulonglong2*)&sm.p.sS[d][bh * 8 + 4];
                ffma2(acc[0], wp, q0.x);  ffma2(acc[1], wp, q0.y);
                ffma2(acc[2], wp, q1.x);  ffma2(acc[3], wp, q1.y);
            }

            // Store partial: 8 consecutive floats (2 STG.128).
            {
                float res[8];
#pragma unroll
                for (int j = 0; j < 4; ++j)
                    asm("mov.b64 {%0, %1}, %2;"
                        : "=f"(res[2 * j]), "=f"(res[2 * j + 1]) : "l"(acc[j]));
                float* dst = &g_part[q][ch][ks][row][bh * 8];
                *(float4*)(dst)     = make_float4(res[0], res[1], res[2], res[3]);
                *(float4*)(dst + 4) = make_float4(res[4], res[5], res[6], res[7]);
            }

            __threadfence();
            __syncthreads();
            if (t == 0) s_tk = atomicAdd(&g_cnt[q][ch], 1);
            __syncthreads();

            if (s_tk == PKS - 1) {
                // Last finisher reduces chunk (q,ch) in FIXED ks order.
                const int o = obase + row;
                const float bo = bias[o];
                float v[8];
#pragma unroll
                for (int j = 0; j < 8; ++j) v[j] = bo;
#pragma unroll 8
                for (int k2 = 0; k2 < PKS; ++k2) {
                    const float4* pp =
                        (const float4*)&g_part[q][ch][k2][row][bh * 8];
                    const float4 a = __ldcg(pp);
                    const float4 bq = __ldcg(pp + 1);
                    v[0] += a.x;  v[1] += a.y;  v[2] += a.z;  v[3] += a.w;
                    v[4] += bq.x; v[5] += bq.y; v[6] += bq.z; v[7] += bq.w;
                }
#pragma unroll
                for (int j = 0; j < 8; ++j)
                    g_altered[(bh * 8 + j) * DDIM + o] = v[j];

                __threadfence();
                __syncthreads();
                if (t == 0) {
                    g_cnt[q][ch] = 0;                 // self-reset
                    atomicAdd(&g_qdone[q], 1);        // quarter ready at ==PCH
                }
            }
        }
        return;
    }

    // ================= Consumer: stream enc quarter-by-quarter =============
    const int cb   = bid - NPROD;
    const int b    = cb & 15;
    const int sg   = cb >> 4;               // 0..127
    const int w    = t >> 5;
    const int lane = t & 31;
    const int s0   = sg * 16 + w * 4;       // 4 s-rows per warp

    const float4* r0 = (const float4*)(enc + ((long)(s0 + 0) * BATCH + b) * DDIM);
    const float4* r1 = (const float4*)(enc + ((long)(s0 + 1) * BATCH + b) * DDIM);
    const float4* r2 = (const float4*)(enc + ((long)(s0 + 2) * BATCH + b) * DDIM);
    const float4* r3 = (const float4*)(enc + ((long)(s0 + 3) * BATCH + b) * DDIM);

    float4 A0 = make_float4(0.f,0.f,0.f,0.f), A1 = A0, A2 = A0, A3 = A0;

    for (int q = 0; q < NQ; ++q) {
        if (t == 0) {
            while (((volatile int*)g_qdone)[q] < PCH) __nanosleep(256);
        }
        __syncthreads();                    // all warps done with prev alt
        __threadfence();
        // Load this quarter of altered[b][:]: 512 floats = 128 f4, 1/thread.
        ((float4*)sm.alt)[t] =
            __ldcg((const float4*)(g_altered + b * DDIM + q * QD) + t);
        __syncthreads();

        const int qf4 = q * (QD / 4);
#pragma unroll
        for (int j = 0; j < QD / 128; ++j) {        // 4 iters, 16 LDG in flight
            const int f4 = j * 32 + lane;
            const float4 a  = ((const float4*)sm.alt)[f4];
            const float4 e0 = __ldcs(r0 + qf4 + f4);
            const float4 e1 = __ldcs(r1 + qf4 + f4);
            const float4 e2 = __ldcs(r2 + qf4 + f4);
            const float4 e3 = __ldcs(r3 + qf4 + f4);
            A0.x += e0.x*a.x; A0.y += e0.y*a.y; A0.z += e0.z*a.z; A0.w += e0.w*a.w;
            A1.x += e1.x*a.x; A1.y += e1.y*a.y; A1.z += e1.z*a.z; A1.w += e1.w*a.w;
            A2.x += e2.x*a.x; A2.y += e2.y*a.y; A2.z += e2.z*a.z; A2.w += e2.w*a.w;
            A3.x += e3.x*a.x; A3.y += e3.y*a.y; A3.z += e3.z*a.z; A3.w += e3.w*a.w;
        }
    }

    float t0 = (A0.x + A0.y) + (A0.z + A0.w);
    float t1 = (A1.x + A1.y) + (A1.z + A1.w);
    float t2 = (A2.x + A2.y) + (A2.z + A2.w);
    float t3 = (A3.x + A3.y) + (A3.z + A3.w);
#pragma unroll
    for (int off = 16; off > 0; off >>= 1) {
        t0 += __shfl_down_sync(0xFFFFFFFFu, t0, off);
        t1 += __shfl_down_sync(0xFFFFFFFFu, t1, off);
        t2 += __shfl_down_sync(0xFFFFFFFFu, t2, off);
        t3 += __shfl_down_sync(0xFFFFFFFFu, t3, off);
    }
    if (lane == 0) {
        out[b * S_LEN + s0 + 0] = t0;
        out[b * S_LEN + s0 + 1] = t1;
        out[b * S_LEN + s0 + 2] = t2;
        out[b * S_LEN + s0 + 3] = t3;
    }

    __syncthreads();
    if (t == 0) {
        const int tk = atomicAdd(&g_s2cnt, 1);
        if (tk == NCONS - 1) {              // last consumer: self-reset
#pragma unroll
            for (int q = 0; q < NQ; ++q) g_qdone[q] = 0;
            g_s2cnt = 0;
        }
    }
}

extern "C" void kernel_launch(void* const* d_in, const int* in_sizes, int n_in,
                              void* d_out, int out_size)
{
    const float* enc   = (const float*)d_in[0];  // [S, B, D]
    const float* state = (const float*)d_in[1];  // [B, D]
    const float* W     = (const float*)d_in[2];  // [D, D]
    const float* bias  = (const float*)d_in[3];  // [D]
    float* out         = (float*)d_out;          // [B, S]

    attender_fused<<<NB, 128>>>(state, W, bias, enc, out);
}

// round 13
// speedup vs baseline: 2.1216x; 2.1216x over previous
#include <cuda_runtime.h>
#include <cuda_bf16.h>
#include <cstdint>

// Problem shapes (fixed by the dataset)
#define S_LEN 2048
#define BATCH 16
#define DDIM  2048

// Stage-1 tiling: 256-thread blocks, thread owns one o row x all 16 b.
#define OTILE   256                 // o rows per block (1 per thread)
#define KSPLIT  64
#define KCHUNK  (DDIM / KSPLIT)     // 32 d per block
#define WPAD    33                  // sW bank = (r + d) % 32 -> conflict-free
#define SPAD    20                  // sS row stride (80B, 16B-aligned LDS.128)

// Scratch (device globals: allocation-free). g_part layout: [kc][o][b].
__device__ float g_part[KSPLIT * DDIM * BATCH];   // 8 MB
__device__ float g_altered[BATCH * DDIM];         // [b][o], 128 KB

__device__ __forceinline__ void ffma2(uint64_t& d, uint64_t a, uint64_t b) {
    asm("fma.rn.f32x2 %0, %1, %2, %0;" : "+l"(d) : "l"(a), "l"(b));
}

// ---------------------------------------------------------------------------
// Kernel 1a: partial[kc][o][b] = sum_{d in chunk kc} state[b][d] * W[o][d]
// 256-thread blocks: grid 512 x 8 warps = ~28 warps/SM (vs 14 before) --
// doubles the independent warps per SMSP to hide LDS/LDG latency.
// Per d per thread: 1 scalar W LDS (bank (t+d)%32, conflict-free) +
// 4 broadcast state LDS.128 + 8 FFMA2 (16 batch accs as packed f32x2).
// ---------------------------------------------------------------------------
__global__ void __launch_bounds__(256)
stage1_part(const float* __restrict__ state,
            const float* __restrict__ W)
{
    __shared__ float sW[OTILE][WPAD];   // 256 x 33 x 4B = 33.8 KB
    __shared__ float sS[KCHUNK][SPAD];  // 2.5 KB

    const int t     = threadIdx.x;      // 0..255 = local o
    const int obase = blockIdx.x * OTILE;
    const int kc    = blockIdx.y;
    const int d0    = kc * KCHUNK;

    // --- Stage state chunk transposed: sS[d][b] (threads 0..127 only).
    if (t < 128) {
        const int b  = t >> 3;
        const int c4 = t & 7;
        const float4 v = *(const float4*)(state + b * DDIM + d0 + c4 * 4);
        sS[c4 * 4 + 0][b] = v.x;
        sS[c4 * 4 + 1][b] = v.y;
        sS[c4 * 4 + 2][b] = v.z;
        sS[c4 * 4 + 3][b] = v.w;
    }

    // --- Stage W tile 256 rows x 32 d: 2048 float4, 8/thread, coalesced
    // (8 lanes per row -> nL=4); STS banks (r + 4*c4 + k) % 32 conflict-free.
#pragma unroll
    for (int j = 0; j < 8; ++j) {
        const int g  = j * 256 + t;
        const int r  = g >> 3;
        const int c4 = g & 7;
        const float4 v = *(const float4*)(W + (long)(obase + r) * DDIM + d0 + c4 * 4);
        sW[r][c4 * 4 + 0] = v.x;
        sW[r][c4 * 4 + 1] = v.y;
        sW[r][c4 * 4 + 2] = v.z;
        sW[r][c4 * 4 + 3] = v.w;
    }
    __syncthreads();

    uint64_t acc[8];                    // 16 batch accs as packed f32x2
#pragma unroll
    for (int i = 0; i < 8; ++i) acc[i] = 0ull;

#pragma unroll 8
    for (int d = 0; d < KCHUNK; ++d) {
        const float w = sW[t][d];       // bank (t+d)%32: conflict-free
        uint64_t wp;
        asm("mov.b64 %0, {%1, %1};" : "=l"(wp) : "r"(__float_as_uint(w)));
        const ulonglong2 q0 = *(const ulonglong2*)&sS[d][0];   // broadcast
        const ulonglong2 q1 = *(const ulonglong2*)&sS[d][4];
        const ulonglong2 q2 = *(const ulonglong2*)&sS[d][8];
        const ulonglong2 q3 = *(const ulonglong2*)&sS[d][12];
        ffma2(acc[0], wp, q0.x);  ffma2(acc[1], wp, q0.y);
        ffma2(acc[2], wp, q1.x);  ffma2(acc[3], wp, q1.y);
        ffma2(acc[4], wp, q2.x);  ffma2(acc[5], wp, q2.y);
        ffma2(acc[6], wp, q3.x);  ffma2(acc[7], wp, q3.y);
    }

    // --- Store partial row: 16 consecutive floats (4 STG.128).
    {
        float res[16];
#pragma unroll
        for (int j = 0; j < 8; ++j)
            asm("mov.b64 {%0, %1}, %2;"
                : "=f"(res[2 * j]), "=f"(res[2 * j + 1]) : "l"(acc[j]));
        float* dst = g_part + ((long)kc * DDIM + obase + t) * BATCH;
#pragma unroll
        for (int q = 0; q < 4; ++q)
            *(float4*)(dst + q * 4) =
                make_float4(res[q * 4], res[q * 4 + 1], res[q * 4 + 2], res[q * 4 + 3]);
    }
}

// ---------------------------------------------------------------------------
// Kernel 1b: altered[b][o] = bias[o] + sum_kc partial[kc][o][b]
// 8 MB streamed, coalesced, deterministic fixed-order sum.
// ---------------------------------------------------------------------------
__global__ void __launch_bounds__(256)
stage1_reduce(const float* __restrict__ bias)
{
    const int n = blockIdx.x * 256 + threadIdx.x;   // 0..32767
    const int o = n >> 4;
    const int b = n & 15;
    float v = bias[o];
#pragma unroll
    for (int kc = 0; kc < KSPLIT; ++kc)
        v += g_part[(long)kc * DDIM * BATCH + n];
    g_altered[b * DDIM + o] = v;
}

// ---------------------------------------------------------------------------
// Kernel 2: weights[b][s] = sum_d altered[b][d] * enc[s][b][d]
// Streaming __ldcs loads; proven at the ~6.4 TB/s LTS chip cap.
// ---------------------------------------------------------------------------
__global__ void __launch_bounds__(256, 8)
stage2_dots(const float* __restrict__ enc,
            float* __restrict__ out)
{
    __shared__ float alt[DDIM];

    const int tid    = threadIdx.x;
    const int warpId = tid >> 5;
    const int lane   = tid & 31;
    const int b      = blockIdx.y;
    const int s      = blockIdx.x * 8 + warpId;

#pragma unroll
    for (int j = 0; j < 2; ++j) {
        int f4 = tid + j * 256;
        *(float4*)&alt[f4 * 4] = *(const float4*)(g_altered + b * DDIM + f4 * 4);
    }
    __syncthreads();

    const float4* row = (const float4*)(enc + ((long)s * BATCH + b) * DDIM);

    float4 acc = make_float4(0.f, 0.f, 0.f, 0.f);
#pragma unroll
    for (int i = 0; i < 16; ++i) {
        const int f4 = i * 32 + lane;
        const float4 e = __ldcs(row + f4);          // streaming load
        const float4 a = *(const float4*)&alt[f4 * 4];
        acc.x += e.x * a.x;
        acc.y += e.y * a.y;
        acc.z += e.z * a.z;
        acc.w += e.w * a.w;
    }

    float tt = (acc.x + acc.y) + (acc.z + acc.w);
#pragma unroll
    for (int off = 16; off > 0; off >>= 1)
        tt += __shfl_down_sync(0xFFFFFFFFu, tt, off);

    if (lane == 0)
        out[b * S_LEN + s] = tt;   // output shape [B, S]
}

extern "C" void kernel_launch(void* const* d_in, const int* in_sizes, int n_in,
                              void* d_out, int out_size)
{
    const float* enc   = (const float*)d_in[0];  // [S, B, D]
    const float* state = (const float*)d_in[1];  // [B, D]
    const float* W     = (const float*)d_in[2];  // [D, D]
    const float* bias  = (const float*)d_in[3];  // [D]
    float* out         = (float*)d_out;          // [B, S]

    stage1_part<<<dim3(DDIM / OTILE, KSPLIT), 256>>>(state, W);
    stage1_reduce<<<(BATCH * DDIM) / 256, 256>>>(bias);
    stage2_dots<<<dim3(S_LEN / 8, BATCH), 256>>>(enc, out);
}